// round 4
// baseline (speedup 1.0000x reference)
#include <cuda_runtime.h>
#include <cstdint>
#include <cstring>

// Problem dims
#define IN_F   4096
#define OUT_F  16384
#define MROWS  2048

// Quantization: x ~= DELTA * (256*h + l), h,l int8
static constexpr float XMAX   = 8.0f;
static constexpr float QMAXF  = 32512.0f;          // 127*256 + 128 headroom-safe
static constexpr float INV_D  = QMAXF / XMAX;      // 4064
static constexpr float DELTA  = XMAX / QMAXF;

// GEMM tiling
static constexpr int BM = 128;
static constexpr int BN = 128;
static constexpr int BK = 128;                     // == group size GS
static constexpr int STAGES = 4;
static constexpr int KITERS = IN_F / BK;           // 32
static constexpr int TILE_BYTES = 128 * 128;       // 16 KB per tile
static constexpr int STAGE_BYTES = 3 * TILE_BYTES; // Ah, Al, B
static constexpr int SMEM_TOTAL = STAGES * STAGE_BYTES;  // 196608

// ── Scratch (device globals; no allocation) ──────────────────────────────
__device__ int8_t g_Xh[(size_t)MROWS * IN_F];
__device__ int8_t g_Xl[(size_t)MROWS * IN_F];
__device__ int8_t g_W8[(size_t)OUT_F * IN_F];

// ── PTX helpers (sm_80-level only; no 'a'-gated features) ────────────────
__device__ __forceinline__ uint32_t smem_u32(const void* p) {
    uint32_t a;
    asm("{ .reg .u64 t; cvta.to.shared.u64 t, %1; cvt.u32.u64 %0, t; }" : "=r"(a) : "l"(p));
    return a;
}
#define CP_ASYNC16(dst, src) \
    asm volatile("cp.async.cg.shared.global [%0], [%1], 16;" :: "r"(dst), "l"(src))
#define CP_COMMIT() asm volatile("cp.async.commit_group;" ::: "memory")
#define CP_WAIT2()  asm volatile("cp.async.wait_group 2;" ::: "memory")

__device__ __forceinline__ void ldsm4(uint32_t& r0, uint32_t& r1, uint32_t& r2, uint32_t& r3,
                                      uint32_t addr) {
    asm volatile("ldmatrix.sync.aligned.m8n8.x4.shared.b16 {%0,%1,%2,%3}, [%4];"
                 : "=r"(r0), "=r"(r1), "=r"(r2), "=r"(r3) : "r"(addr));
}
#define IMMA(c, a0, a1, a2, a3, b0, b1)                                     \
    asm volatile("mma.sync.aligned.m16n8k32.row.col.s32.s8.s8.s32 "         \
                 "{%0,%1,%2,%3},{%4,%5,%6,%7},{%8,%9},{%0,%1,%2,%3};"       \
                 : "+r"((c)[0]), "+r"((c)[1]), "+r"((c)[2]), "+r"((c)[3])   \
                 : "r"(a0), "r"(a1), "r"(a2), "r"(a3), "r"(b0), "r"(b1))

// physical swizzled byte offset of (row, 16B-chunk) inside a 128x128B tile
__device__ __forceinline__ uint32_t swz(uint32_t row, uint32_t chunk) {
    return row * 128u + ((chunk ^ (row & 7u)) << 4);
}

// ── Prep: quantize x into two int8 digits ────────────────────────────────
__global__ void prep_x_kernel(const float* __restrict__ x) {
    size_t i = ((size_t)blockIdx.x * blockDim.x + threadIdx.x) * 8;
    const float4* x4 = reinterpret_cast<const float4*>(x + i);
    float4 a = x4[0], b = x4[1];
    float v[8] = {a.x, a.y, a.z, a.w, b.x, b.y, b.z, b.w};
    union { int8_t c[8]; uint2 u; } hh, ll;
#pragma unroll
    for (int j = 0; j < 8; j++) {
        float f = fminf(fmaxf(v[j] * INV_D, -QMAXF), QMAXF);
        int q = __float2int_rn(f);
        int h = (q + 128) >> 8;          // floor((q+128)/256): h in [-127,127]
        int l = q - (h << 8);            // l in [-128,127]
        hh.c[j] = (int8_t)h;
        ll.c[j] = (int8_t)l;
    }
    *reinterpret_cast<uint2*>(&g_Xh[i]) = hh.u;
    *reinterpret_cast<uint2*>(&g_Xl[i]) = ll.u;
}

// ── Prep: ternary int32 -> int8 ──────────────────────────────────────────
__global__ void prep_w_kernel(const int* __restrict__ tern) {
    size_t i = ((size_t)blockIdx.x * blockDim.x + threadIdx.x) * 16;
    const int4* t4 = reinterpret_cast<const int4*>(tern + i);
    union { int8_t c[16]; uint4 u; } w;
#pragma unroll
    for (int q = 0; q < 4; q++) {
        int4 t = t4[q];
        w.c[q * 4 + 0] = (int8_t)t.x;
        w.c[q * 4 + 1] = (int8_t)t.y;
        w.c[q * 4 + 2] = (int8_t)t.z;
        w.c[q * 4 + 3] = (int8_t)t.w;
    }
    *reinterpret_cast<uint4*>(&g_W8[i]) = w.u;
}

// ── GEMM: out[m][n] = DELTA * sum_g s[n,g]*(256*Ph + Pl) ─────────────────
extern __shared__ __align__(128) char smem_raw[];

__global__ void __launch_bounds__(256, 1) qsgd_gemm(
    const float* __restrict__ scales, float* __restrict__ out)
{
    const int8_t* Xh = g_Xh;
    const int8_t* Xl = g_Xl;
    const int8_t* W8 = g_W8;
    uint32_t sb = smem_u32(smem_raw);

    int tid = threadIdx.x, lane = tid & 31, wid = tid >> 5;
    int wm = wid & 1, wn = wid >> 1;          // warp grid 2(m) x 4(n)
    int gID = lane >> 2, tig = lane & 3;
    int mt0 = blockIdx.x, nt0 = blockIdx.y;   // m fastest in grid

    // ---- cp.async source/dest addressing (per thread: 4 rows x 1 chunk per tile)
    // thread t covers rows (t>>3) + 32*j, chunk t&7
    int ld_row = tid >> 3, ld_chunk = tid & 7;
    const int8_t* gA_h = Xh + (size_t)(mt0 * BM + ld_row) * IN_F + ld_chunk * 16;
    const int8_t* gA_l = Xl + (size_t)(mt0 * BM + ld_row) * IN_F + ld_chunk * 16;
    const int8_t* gB   = W8 + (size_t)(nt0 * BN + ld_row) * IN_F + ld_chunk * 16;
    uint32_t st_off[4];
#pragma unroll
    for (int j = 0; j < 4; j++) st_off[j] = swz(ld_row + 32 * j, ld_chunk);

    // ---- ldmatrix per-lane address components
    // A x4: m0 = rows 0-7/chunk0, m1 = rows 8-15/chunk0, m2 = rows 0-7/chunk1, m3 = rows 8-15/chunk1
    uint32_t a_row_base = wm * 64 + (lane & 7) + ((lane >> 3) & 1) * 8;
    uint32_t a_cbit = (uint32_t)(lane >> 4);
    // B x4: m0 = n0-7/chunk0 (b0), m1 = n0-7/chunk1 (b1), m2 = n8-15/chunk0, m3 = n8-15/chunk1
    uint32_t b_row_base = wn * 32 + (lane & 7) + ((lane >> 4) & 1) * 8;
    uint32_t b_cbit = (uint32_t)((lane >> 3) & 1);
    uint32_t a_r7 = a_row_base & 7, b_r7 = b_row_base & 7;

    // ---- scale index bases: 8 (ntile, col) pairs per lane
    int nbase[8];
#pragma unroll
    for (int nt = 0; nt < 4; nt++)
#pragma unroll
        for (int c = 0; c < 2; c++) {
            int n_g = nt0 * BN + wn * 32 + nt * 8 + tig * 2 + c;
            nbase[nt * 2 + c] = n_g * (IN_F / 128);
        }

    float fa[4][4][4];
#pragma unroll
    for (int mt = 0; mt < 4; mt++)
#pragma unroll
        for (int nt = 0; nt < 4; nt++)
#pragma unroll
            for (int r = 0; r < 4; r++) fa[mt][nt][r] = 0.0f;

    // ---- pipeline prologue: stages 0..2
#pragma unroll
    for (int p = 0; p < STAGES - 1; p++) {
        uint32_t s_a = sb + p * STAGE_BYTES;
#pragma unroll
        for (int j = 0; j < 4; j++) {
            size_t go = (size_t)(32 * j) * IN_F + (size_t)p * BK;
            CP_ASYNC16(s_a + st_off[j],                  gA_h + go);
            CP_ASYNC16(s_a + TILE_BYTES + st_off[j],     gA_l + go);
            CP_ASYNC16(s_a + 2 * TILE_BYTES + st_off[j], gB + go);
        }
        CP_COMMIT();
    }

    // ---- main loop over 32 k-groups (each k-group = 1 scale group, 4 k32 mma steps)
    for (int it = 0; it < KITERS; it++) {
        CP_WAIT2();
        __syncthreads();

        // issue stage it+3
        if (it + STAGES - 1 < KITERS) {
            int p = (it + STAGES - 1) % STAGES;
            uint32_t s_a = sb + p * STAGE_BYTES;
#pragma unroll
            for (int j = 0; j < 4; j++) {
                size_t go = (size_t)(32 * j) * IN_F + (size_t)(it + STAGES - 1) * BK;
                CP_ASYNC16(s_a + st_off[j],                  gA_h + go);
                CP_ASYNC16(s_a + TILE_BYTES + st_off[j],     gA_l + go);
                CP_ASYNC16(s_a + 2 * TILE_BYTES + st_off[j], gB + go);
            }
        }
        CP_COMMIT();

        // load the 8 group scales for this iter (hits L2)
        float sc[8];
#pragma unroll
        for (int i8 = 0; i8 < 8; i8++) sc[i8] = __ldg(&scales[nbase[i8] + it]);

        uint32_t stg = sb + (it % STAGES) * STAGE_BYTES;
        uint32_t sB = stg + 2 * TILE_BYTES;

#pragma unroll
        for (int pass = 0; pass < 2; pass++) {
            uint32_t sA = stg + (pass ? TILE_BYTES : 0);
            int ia[4][4][4];
#pragma unroll
            for (int mt = 0; mt < 4; mt++)
#pragma unroll
                for (int nt = 0; nt < 4; nt++)
#pragma unroll
                    for (int r = 0; r < 4; r++) ia[mt][nt][r] = 0;

            // 4 k32 steps cover this BK=128 group; chunk index 2*ks+cbit in [0,7]
#pragma unroll
            for (int ks = 0; ks < 4; ks++) {
                // A fragments: 4 m16 tiles
                uint32_t af[4][4];
#pragma unroll
                for (int mt = 0; mt < 4; mt++) {
                    uint32_t row = a_row_base + mt * 16;
                    uint32_t addr = sA + row * 128u +
                                    (((2u * ks + a_cbit) ^ a_r7) << 4);
                    ldsm4(af[mt][0], af[mt][1], af[mt][2], af[mt][3], addr);
                }
                // B fragments: 2 x4 loads cover 4 n8 tiles
                uint32_t bf[4][2];
#pragma unroll
                for (int nt2 = 0; nt2 < 2; nt2++) {
                    uint32_t row = b_row_base + nt2 * 16;
                    uint32_t addr = sB + row * 128u +
                                    (((2u * ks + b_cbit) ^ b_r7) << 4);
                    uint32_t r0, r1, r2, r3;
                    ldsm4(r0, r1, r2, r3, addr);
                    bf[nt2 * 2 + 0][0] = r0; bf[nt2 * 2 + 0][1] = r1;
                    bf[nt2 * 2 + 1][0] = r2; bf[nt2 * 2 + 1][1] = r3;
                }
#pragma unroll
                for (int mt = 0; mt < 4; mt++)
#pragma unroll
                    for (int nt = 0; nt < 4; nt++)
                        IMMA(ia[mt][nt], af[mt][0], af[mt][1], af[mt][2], af[mt][3],
                             bf[nt][0], bf[nt][1]);
            }

            // merge integer partials with group scale (exact: |ia| <= 127*128*256)
            float wt = pass ? 1.0f : 256.0f;
#pragma unroll
            for (int mt = 0; mt < 4; mt++)
#pragma unroll
                for (int nt = 0; nt < 4; nt++)
#pragma unroll
                    for (int r = 0; r < 4; r++)
                        fa[mt][nt][r] += (wt * sc[nt * 2 + (r & 1)]) * (float)ia[mt][nt][r];
        }
    }

    // ---- epilogue: out = DELTA * fa
#pragma unroll
    for (int mt = 0; mt < 4; mt++)
#pragma unroll
        for (int rr = 0; rr < 2; rr++) {
            int m_g = mt0 * BM + wm * 64 + mt * 16 + gID + rr * 8;
            float* op = out + (size_t)m_g * OUT_F + nt0 * BN + wn * 32 + tig * 2;
#pragma unroll
            for (int nt = 0; nt < 4; nt++) {
                float2 v;
                v.x = DELTA * fa[mt][nt][rr * 2 + 0];
                v.y = DELTA * fa[mt][nt][rr * 2 + 1];
                *reinterpret_cast<float2*>(op + nt * 8) = v;
            }
        }
}

// ── Host ─────────────────────────────────────────────────────────────────
extern "C" void kernel_launch(void* const* d_in, const int* in_sizes, int n_in,
                              void* d_out, int out_size) {
    const float* x      = (const float*)d_in[0];
    const int*   tern   = (const int*)d_in[1];
    const float* scales = (const float*)d_in[2];
    float* out = (float*)d_out;

    prep_x_kernel<<<((size_t)MROWS * IN_F) / (256 * 8), 256>>>(x);
    prep_w_kernel<<<((size_t)OUT_F * IN_F) / (256 * 16), 256>>>(tern);

    cudaFuncSetAttribute((const void*)qsgd_gemm,
                         cudaFuncAttributeMaxDynamicSharedMemorySize, SMEM_TOTAL);
    // grid: x = M tiles (fastest) so the 16 M-CTAs of one N-column run
    // concurrently and share the W tiles through L2
    qsgd_gemm<<<dim3(MROWS / BM, OUT_F / BN), 256, SMEM_TOTAL>>>(scales, out);
}

// round 6
// speedup vs baseline: 1.0624x; 1.0624x over previous
#include <cuda_runtime.h>
#include <cstdint>
#include <cstring>

// Problem dims
#define IN_F   4096
#define OUT_F  16384
#define MROWS  2048

// Quantization: x ~= DELTA * (256*h + l), h,l int8
static constexpr float XMAX   = 8.0f;
static constexpr float QMAXF  = 32512.0f;          // 127*256 + 128 headroom-safe
static constexpr float INV_D  = QMAXF / XMAX;
static constexpr float DELTA  = XMAX / QMAXF;

// GEMM tiling: BM=128, BN=64, BK=128 (= group size), 2-stage double buffer
static constexpr int BM = 128;
static constexpr int BN = 64;
static constexpr int BK = 128;
static constexpr int KITERS = IN_F / BK;           // 32
static constexpr int A_TILE  = BM * 128;           // 16 KB (one digit)
static constexpr int B_TILE  = BN * 128;           // 8 KB
static constexpr int STAGE_BYTES = 2 * A_TILE + B_TILE;  // 40960
static constexpr int SMEM_TOTAL  = 2 * STAGE_BYTES;      // 81920 -> 2 CTAs/SM

// ── Scratch (device globals; no allocation) ──────────────────────────────
__device__ int8_t g_Xh[(size_t)MROWS * IN_F];
__device__ int8_t g_Xl[(size_t)MROWS * IN_F];
__device__ int8_t g_W8[(size_t)OUT_F * IN_F];

// ── PTX helpers (sm_80-level only) ───────────────────────────────────────
__device__ __forceinline__ uint32_t smem_u32(const void* p) {
    uint32_t a;
    asm("{ .reg .u64 t; cvta.to.shared.u64 t, %1; cvt.u32.u64 %0, t; }" : "=r"(a) : "l"(p));
    return a;
}
#define CP_ASYNC16(dst, src) \
    asm volatile("cp.async.cg.shared.global [%0], [%1], 16;" :: "r"(dst), "l"(src))
#define CP_COMMIT() asm volatile("cp.async.commit_group;" ::: "memory")
#define CP_WAIT1()  asm volatile("cp.async.wait_group 1;" ::: "memory")

__device__ __forceinline__ void ldsm4(uint32_t& r0, uint32_t& r1, uint32_t& r2, uint32_t& r3,
                                      uint32_t addr) {
    asm volatile("ldmatrix.sync.aligned.m8n8.x4.shared.b16 {%0,%1,%2,%3}, [%4];"
                 : "=r"(r0), "=r"(r1), "=r"(r2), "=r"(r3) : "r"(addr));
}
#define IMMA(c, a0, a1, a2, a3, b0, b1)                                     \
    asm volatile("mma.sync.aligned.m16n8k32.row.col.s32.s8.s8.s32 "         \
                 "{%0,%1,%2,%3},{%4,%5,%6,%7},{%8,%9},{%0,%1,%2,%3};"       \
                 : "+r"((c)[0]), "+r"((c)[1]), "+r"((c)[2]), "+r"((c)[3])   \
                 : "r"(a0), "r"(a1), "r"(a2), "r"(a3), "r"(b0), "r"(b1))

// swizzled byte offset of (row, 16B-chunk) inside a rows x 128B tile
__device__ __forceinline__ uint32_t swz(uint32_t row, uint32_t chunk) {
    return row * 128u + ((chunk ^ (row & 7u)) << 4);
}

// ── Prep: quantize x into two int8 digits ────────────────────────────────
__global__ void prep_x_kernel(const float* __restrict__ x) {
    size_t i = ((size_t)blockIdx.x * blockDim.x + threadIdx.x) * 8;
    const float4* x4 = reinterpret_cast<const float4*>(x + i);
    float4 a = x4[0], b = x4[1];
    float v[8] = {a.x, a.y, a.z, a.w, b.x, b.y, b.z, b.w};
    union { int8_t c[8]; uint2 u; } hh, ll;
#pragma unroll
    for (int j = 0; j < 8; j++) {
        float f = fminf(fmaxf(v[j] * INV_D, -QMAXF), QMAXF);
        int q = __float2int_rn(f);
        int h = (q + 128) >> 8;
        int l = q - (h << 8);
        hh.c[j] = (int8_t)h;
        ll.c[j] = (int8_t)l;
    }
    *reinterpret_cast<uint2*>(&g_Xh[i]) = hh.u;
    *reinterpret_cast<uint2*>(&g_Xl[i]) = ll.u;
}

// ── Prep: ternary int32 -> int8 ──────────────────────────────────────────
__global__ void prep_w_kernel(const int* __restrict__ tern) {
    size_t i = ((size_t)blockIdx.x * blockDim.x + threadIdx.x) * 16;
    const int4* t4 = reinterpret_cast<const int4*>(tern + i);
    union { int8_t c[16]; uint4 u; } w;
#pragma unroll
    for (int q = 0; q < 4; q++) {
        int4 t = t4[q];
        w.c[q * 4 + 0] = (int8_t)t.x;
        w.c[q * 4 + 1] = (int8_t)t.y;
        w.c[q * 4 + 2] = (int8_t)t.z;
        w.c[q * 4 + 3] = (int8_t)t.w;
    }
    *reinterpret_cast<uint4*>(&g_W8[i]) = w.u;
}

// ── GEMM: out[m][n] = DELTA * sum_g s[n,g]*(256*Ph + Pl) ─────────────────
extern __shared__ __align__(128) char smem_raw[];

__global__ void __launch_bounds__(256, 2) qsgd_gemm(
    const float* __restrict__ scales, float* __restrict__ out)
{
    uint32_t sb = smem_u32(smem_raw);

    int tid = threadIdx.x, lane = tid & 31, wid = tid >> 5;
    int wm = wid & 1, wn = wid >> 1;          // warp grid 2(m) x 4(n), warp tile 64x16
    int gID = lane >> 2, tig = lane & 3;
    int mt0 = blockIdx.x, nt0 = blockIdx.y;   // m fastest in grid

    // ---- cp.async addressing: thread t -> row (t>>3)+32j, chunk t&7
    int ld_row = tid >> 3, ld_chunk = tid & 7;
    const int8_t* gA_h = g_Xh + (size_t)(mt0 * BM + ld_row) * IN_F + ld_chunk * 16;
    const int8_t* gA_l = g_Xl + (size_t)(mt0 * BM + ld_row) * IN_F + ld_chunk * 16;
    const int8_t* gB   = g_W8 + (size_t)(nt0 * BN + ld_row) * IN_F + ld_chunk * 16;
    uint32_t st_off[4];
#pragma unroll
    for (int j = 0; j < 4; j++) st_off[j] = swz(ld_row + 32 * j, ld_chunk);

    // ---- ldmatrix per-lane address components (same fragment mapping as R4)
    uint32_t a_row_base = wm * 64 + (lane & 7) + ((lane >> 3) & 1) * 8;
    uint32_t a_cbit = (uint32_t)(lane >> 4);
    uint32_t b_row_base = wn * 16 + (lane & 7) + ((lane >> 4) & 1) * 8;
    uint32_t b_cbit = (uint32_t)((lane >> 3) & 1);
    uint32_t a_r7 = a_row_base & 7, b_r7 = b_row_base & 7;

    // ---- scale index bases: 4 (ntile, col) pairs per lane
    int nbase[4];
#pragma unroll
    for (int nt = 0; nt < 2; nt++)
#pragma unroll
        for (int c = 0; c < 2; c++) {
            int n_g = nt0 * BN + wn * 16 + nt * 8 + tig * 2 + c;
            nbase[nt * 2 + c] = n_g * (IN_F / 128);
        }

    float fa[4][2][4];
#pragma unroll
    for (int mt = 0; mt < 4; mt++)
#pragma unroll
        for (int nt = 0; nt < 2; nt++)
#pragma unroll
            for (int r = 0; r < 4; r++) fa[mt][nt][r] = 0.0f;

    // ---- prologue: load stage 0
    {
        uint32_t s_a = sb;
#pragma unroll
        for (int j = 0; j < 4; j++) {
            size_t go = (size_t)(32 * j) * IN_F;
            CP_ASYNC16(s_a + st_off[j],          gA_h + go);
            CP_ASYNC16(s_a + A_TILE + st_off[j], gA_l + go);
            if (j < 2) CP_ASYNC16(s_a + 2 * A_TILE + st_off[j], gB + go);
        }
        CP_COMMIT();
    }

    // ---- main loop
    for (int it = 0; it < KITERS; it++) {
        // free the buffer we are about to overwrite (read by all warps last iter)
        if (it > 0) __syncthreads();

        if (it + 1 < KITERS) {
            uint32_t s_a = sb + ((it + 1) & 1) * STAGE_BYTES;
            size_t kb = (size_t)(it + 1) * BK;
#pragma unroll
            for (int j = 0; j < 4; j++) {
                size_t go = (size_t)(32 * j) * IN_F + kb;
                CP_ASYNC16(s_a + st_off[j],          gA_h + go);
                CP_ASYNC16(s_a + A_TILE + st_off[j], gA_l + go);
                if (j < 2) CP_ASYNC16(s_a + 2 * A_TILE + st_off[j], gB + go);
            }
        }
        CP_COMMIT();
        CP_WAIT1();            // stage `it` complete
        __syncthreads();

        // group scales for this k-group (L2-resident)
        float sclo[4], schi[4];
#pragma unroll
        for (int i4 = 0; i4 < 4; i4++) {
            float s = __ldg(&scales[nbase[i4] + it]);
            sclo[i4] = s;
            schi[i4] = 256.0f * s;
        }

        uint32_t stg = sb + (it & 1) * STAGE_BYTES;
        uint32_t sB = stg + 2 * A_TILE;

#pragma unroll
        for (int pass = 0; pass < 2; pass++) {
            uint32_t sA = stg + (pass ? A_TILE : 0);
            int ia[4][2][4];
#pragma unroll
            for (int mt = 0; mt < 4; mt++)
#pragma unroll
                for (int nt = 0; nt < 2; nt++)
#pragma unroll
                    for (int r = 0; r < 4; r++) ia[mt][nt][r] = 0;

            // 4 k32 steps cover this 128-wide scale group
#pragma unroll
            for (int ks = 0; ks < 4; ks++) {
                uint32_t af[4][4];
#pragma unroll
                for (int mt = 0; mt < 4; mt++) {
                    uint32_t row = a_row_base + mt * 16;
                    uint32_t addr = sA + row * 128u + (((2u * ks + a_cbit) ^ a_r7) << 4);
                    ldsm4(af[mt][0], af[mt][1], af[mt][2], af[mt][3], addr);
                }
                uint32_t bf[2][2];
                {
                    uint32_t addr = sB + b_row_base * 128u + (((2u * ks + b_cbit) ^ b_r7) << 4);
                    uint32_t r0, r1, r2, r3;
                    ldsm4(r0, r1, r2, r3, addr);
                    bf[0][0] = r0; bf[0][1] = r1;
                    bf[1][0] = r2; bf[1][1] = r3;
                }
#pragma unroll
                for (int mt = 0; mt < 4; mt++)
#pragma unroll
                    for (int nt = 0; nt < 2; nt++)
                        IMMA(ia[mt][nt], af[mt][0], af[mt][1], af[mt][2], af[mt][3],
                             bf[nt][0], bf[nt][1]);
            }

            const float* sc = pass ? sclo : schi;
#pragma unroll
            for (int mt = 0; mt < 4; mt++)
#pragma unroll
                for (int nt = 0; nt < 2; nt++)
#pragma unroll
                    for (int r = 0; r < 4; r++)
                        fa[mt][nt][r] += sc[nt * 2 + (r & 1)] * (float)ia[mt][nt][r];
        }
    }

    // ---- epilogue: out = DELTA * fa
#pragma unroll
    for (int mt = 0; mt < 4; mt++)
#pragma unroll
        for (int rr = 0; rr < 2; rr++) {
            int m_g = mt0 * BM + wm * 64 + mt * 16 + gID + rr * 8;
            float* op = out + (size_t)m_g * OUT_F + nt0 * BN + wn * 16 + tig * 2;
#pragma unroll
            for (int nt = 0; nt < 2; nt++) {
                float2 v;
                v.x = DELTA * fa[mt][nt][rr * 2 + 0];
                v.y = DELTA * fa[mt][nt][rr * 2 + 1];
                *reinterpret_cast<float2*>(op + nt * 8) = v;
            }
        }
}

// ── Host ─────────────────────────────────────────────────────────────────
extern "C" void kernel_launch(void* const* d_in, const int* in_sizes, int n_in,
                              void* d_out, int out_size) {
    const float* x      = (const float*)d_in[0];
    const int*   tern   = (const int*)d_in[1];
    const float* scales = (const float*)d_in[2];
    float* out = (float*)d_out;

    prep_x_kernel<<<((size_t)MROWS * IN_F) / (256 * 8), 256>>>(x);
    prep_w_kernel<<<((size_t)OUT_F * IN_F) / (256 * 16), 256>>>(tern);

    cudaFuncSetAttribute((const void*)qsgd_gemm,
                         cudaFuncAttributeMaxDynamicSharedMemorySize, SMEM_TOTAL);
    // grid: x = M tiles (fastest) so concurrent CTAs share W/X tiles via L2
    qsgd_gemm<<<dim3(MROWS / BM, OUT_F / BN), 256, SMEM_TOTAL>>>(scales, out);
}

// round 7
// speedup vs baseline: 5.7766x; 5.4371x over previous
#include <cuda_runtime.h>
#include <cuda_fp16.h>
#include <cstdint>

// Problem dims
#define IN_F   4096
#define OUT_F  16384
#define MROWS  2048

// GEMM tiling: BM=128, BN=128, BK=64 (fp16 -> 128B rows), 3-stage pipeline
static constexpr int BM = 128;
static constexpr int BN = 128;
static constexpr int BK = 64;
static constexpr int KITERS = IN_F / BK;                 // 64
static constexpr int A_TILE = BM * BK * 2;               // 16 KB
static constexpr int B_TILE = BN * BK * 2;               // 16 KB
static constexpr int STAGE_BYTES = A_TILE + B_TILE;      // 32 KB
static constexpr int STAGES = 3;
static constexpr int SMEM_TOTAL = STAGES * STAGE_BYTES;  // 98304 -> 2 CTAs/SM

// ── Scratch (device globals; no allocation) ──────────────────────────────
__device__ __half g_X16[(size_t)MROWS * IN_F];
__device__ __half g_W16[(size_t)OUT_F * IN_F];

// ── PTX helpers (sm_80-level only; family-portable) ──────────────────────
__device__ __forceinline__ uint32_t smem_u32(const void* p) {
    uint32_t a;
    asm("{ .reg .u64 t; cvta.to.shared.u64 t, %1; cvt.u32.u64 %0, t; }" : "=r"(a) : "l"(p));
    return a;
}
#define CP_ASYNC16(dst, src) \
    asm volatile("cp.async.cg.shared.global [%0], [%1], 16;" :: "r"(dst), "l"(src))
#define CP_COMMIT() asm volatile("cp.async.commit_group;" ::: "memory")
#define CP_WAIT2()  asm volatile("cp.async.wait_group 2;" ::: "memory")

__device__ __forceinline__ void ldsm4(uint32_t& r0, uint32_t& r1, uint32_t& r2, uint32_t& r3,
                                      uint32_t addr) {
    asm volatile("ldmatrix.sync.aligned.m8n8.x4.shared.b16 {%0,%1,%2,%3}, [%4];"
                 : "=r"(r0), "=r"(r1), "=r"(r2), "=r"(r3) : "r"(addr));
}
#define HMMA(c, a0, a1, a2, a3, b0, b1)                                       \
    asm volatile("mma.sync.aligned.m16n8k16.row.col.f32.f16.f16.f32 "         \
                 "{%0,%1,%2,%3},{%4,%5,%6,%7},{%8,%9},{%0,%1,%2,%3};"         \
                 : "+f"((c)[0]), "+f"((c)[1]), "+f"((c)[2]), "+f"((c)[3])     \
                 : "r"(a0), "r"(a1), "r"(a2), "r"(a3), "r"(b0), "r"(b1))

// swizzled byte offset of (row, 16B-chunk) inside a rows x 128B tile
__device__ __forceinline__ uint32_t swz(uint32_t row, uint32_t chunk) {
    return row * 128u + ((chunk ^ (row & 7u)) << 4);
}

// ── Prep: x fp32 -> fp16 ─────────────────────────────────────────────────
__global__ void prep_x_kernel(const float* __restrict__ x) {
    size_t i = ((size_t)blockIdx.x * blockDim.x + threadIdx.x) * 8;
    const float4* x4 = reinterpret_cast<const float4*>(x + i);
    float4 a = x4[0], b = x4[1];
    float v[8] = {a.x, a.y, a.z, a.w, b.x, b.y, b.z, b.w};
    union { __half h[8]; uint4 u; } o;
#pragma unroll
    for (int j = 0; j < 8; j++) o.h[j] = __float2half(v[j]);
    *reinterpret_cast<uint4*>(&g_X16[i]) = o.u;
}

// ── Prep: W16 = ternary * fp16(scale)  (exact: t in {-1,0,1}) ────────────
__global__ void prep_w_kernel(const int* __restrict__ tern, const float* __restrict__ scales) {
    size_t i = ((size_t)blockIdx.x * blockDim.x + threadIdx.x) * 8;   // 8 elems, one group
    const int4* t4 = reinterpret_cast<const int4*>(tern + i);
    int4 a = t4[0], b = t4[1];
    float sf = __half2float(__float2half(scales[i >> 7]));
    int t[8] = {a.x, a.y, a.z, a.w, b.x, b.y, b.z, b.w};
    union { __half h[8]; uint4 u; } o;
#pragma unroll
    for (int j = 0; j < 8; j++) o.h[j] = __float2half(sf * (float)t[j]);  // exact
    *reinterpret_cast<uint4*>(&g_W16[i]) = o.u;
}

// ── GEMM: out[M,N] = X16 @ W16^T, fp32 accum in HMMA ─────────────────────
extern __shared__ __align__(128) char smem_raw[];

__global__ void __launch_bounds__(256, 2) qsgd_gemm(float* __restrict__ out)
{
    uint32_t sb = smem_u32(smem_raw);

    int tid = threadIdx.x, lane = tid & 31, wid = tid >> 5;
    int wm = wid & 1, wn = wid >> 1;          // warp grid 2(m) x 4(n): warp tile 64x32
    int gID = lane >> 2, tig = lane & 3;
    int mt0 = blockIdx.x, nt0 = blockIdx.y;   // m fastest in grid

    // ---- cp.async addressing: thread t -> row (t>>3)+32j, chunk t&7 (bytes)
    int ld_row = tid >> 3, ld_chunk = tid & 7;
    const int8_t* gA = reinterpret_cast<const int8_t*>(g_X16) +
                       (size_t)(mt0 * BM + ld_row) * (IN_F * 2) + ld_chunk * 16;
    const int8_t* gB = reinterpret_cast<const int8_t*>(g_W16) +
                       (size_t)(nt0 * BN + ld_row) * (IN_F * 2) + ld_chunk * 16;
    uint32_t st_off[4];
#pragma unroll
    for (int j = 0; j < 4; j++) st_off[j] = swz(ld_row + 32 * j, ld_chunk);

    // ---- ldmatrix per-lane address components
    // A x4 (m16 x k16): row = wm*64 + mt*16 + (lane&15), chunk bit = lane>>4
    uint32_t a_row_base = wm * 64 + (lane & 15);
    uint32_t a_cbit = (uint32_t)(lane >> 4);
    // B x4 (n16 x k16): row = wn*32 + nb*16 + (lane&7) + ((lane>>4)&1)*8, cbit=(lane>>3)&1
    uint32_t b_row_base = wn * 32 + (lane & 7) + ((lane >> 4) & 1) * 8;
    uint32_t b_cbit = (uint32_t)((lane >> 3) & 1);

    float fa[4][4][4];
#pragma unroll
    for (int mt = 0; mt < 4; mt++)
#pragma unroll
        for (int nt = 0; nt < 4; nt++)
#pragma unroll
            for (int r = 0; r < 4; r++) fa[mt][nt][r] = 0.0f;

    // ---- prologue: stages 0,1
#pragma unroll
    for (int p = 0; p < 2; p++) {
        uint32_t s_a = sb + p * STAGE_BYTES;
        size_t kb = (size_t)p * (BK * 2);
#pragma unroll
        for (int j = 0; j < 4; j++) {
            size_t go = (size_t)(32 * j) * (IN_F * 2) + kb;
            CP_ASYNC16(s_a + st_off[j],          gA + go);
            CP_ASYNC16(s_a + A_TILE + st_off[j], gB + go);
        }
        CP_COMMIT();
    }

    // ---- main loop
    for (int it = 0; it < KITERS; it++) {
        if (it > 0) __syncthreads();   // all warps done with buffer (it+2)%3

        if (it + 2 < KITERS) {
            uint32_t s_a = sb + ((it + 2) % STAGES) * STAGE_BYTES;
            size_t kb = (size_t)(it + 2) * (BK * 2);
#pragma unroll
            for (int j = 0; j < 4; j++) {
                size_t go = (size_t)(32 * j) * (IN_F * 2) + kb;
                CP_ASYNC16(s_a + st_off[j],          gA + go);
                CP_ASYNC16(s_a + A_TILE + st_off[j], gB + go);
            }
        }
        CP_COMMIT();
        CP_WAIT2();                    // stage `it` complete
        __syncthreads();

        uint32_t sA = sb + (it % STAGES) * STAGE_BYTES;
        uint32_t sB = sA + A_TILE;

        // 4 k16 steps cover BK=64
#pragma unroll
        for (int ks = 0; ks < 4; ks++) {
            uint32_t af[4][4];
#pragma unroll
            for (int mt = 0; mt < 4; mt++) {
                uint32_t row = a_row_base + mt * 16;
                uint32_t addr = sA + row * 128u + (((2u * ks + a_cbit) ^ (row & 7u)) << 4);
                ldsm4(af[mt][0], af[mt][1], af[mt][2], af[mt][3], addr);
            }
            uint32_t bf[4][2];
#pragma unroll
            for (int nb = 0; nb < 2; nb++) {
                uint32_t row = b_row_base + nb * 16;
                uint32_t addr = sB + row * 128u + (((2u * ks + b_cbit) ^ (row & 7u)) << 4);
                uint32_t r0, r1, r2, r3;
                ldsm4(r0, r1, r2, r3, addr);
                bf[nb * 2 + 0][0] = r0; bf[nb * 2 + 0][1] = r1;
                bf[nb * 2 + 1][0] = r2; bf[nb * 2 + 1][1] = r3;
            }
#pragma unroll
            for (int mt = 0; mt < 4; mt++)
#pragma unroll
                for (int nt = 0; nt < 4; nt++)
                    HMMA(fa[mt][nt], af[mt][0], af[mt][1], af[mt][2], af[mt][3],
                         bf[nt][0], bf[nt][1]);
        }
    }

    // ---- epilogue
#pragma unroll
    for (int mt = 0; mt < 4; mt++)
#pragma unroll
        for (int rr = 0; rr < 2; rr++) {
            int m_g = mt0 * BM + wm * 64 + mt * 16 + gID + rr * 8;
            float* op = out + (size_t)m_g * OUT_F + nt0 * BN + wn * 32 + tig * 2;
#pragma unroll
            for (int nt = 0; nt < 4; nt++) {
                float2 v;
                v.x = fa[mt][nt][rr * 2 + 0];
                v.y = fa[mt][nt][rr * 2 + 1];
                *reinterpret_cast<float2*>(op + nt * 8) = v;
            }
        }
}

// ── Host ─────────────────────────────────────────────────────────────────
extern "C" void kernel_launch(void* const* d_in, const int* in_sizes, int n_in,
                              void* d_out, int out_size) {
    const float* x      = (const float*)d_in[0];
    const int*   tern   = (const int*)d_in[1];
    const float* scales = (const float*)d_in[2];
    float* out = (float*)d_out;

    prep_x_kernel<<<((size_t)MROWS * IN_F) / (256 * 8), 256>>>(x);
    prep_w_kernel<<<((size_t)OUT_F * IN_F) / (256 * 8), 256>>>(tern, scales);

    cudaFuncSetAttribute((const void*)qsgd_gemm,
                         cudaFuncAttributeMaxDynamicSharedMemorySize, SMEM_TOTAL);
    // grid: x = M tiles (fastest) so concurrent CTAs share W tiles via L2
    qsgd_gemm<<<dim3(MROWS / BM, OUT_F / BN), 256, SMEM_TOTAL>>>(out);
}

// round 8
// speedup vs baseline: 5.8018x; 1.0044x over previous
#include <cuda_runtime.h>
#include <cuda_fp16.h>
#include <cstdint>

// Problem dims
#define IN_F   4096
#define OUT_F  16384
#define MROWS  2048

// GEMM tiling: BM=128, BN=128, BK=64 (fp16 -> 128B rows), 3-stage pipeline
static constexpr int BM = 128;
static constexpr int BN = 128;
static constexpr int BK = 64;
static constexpr int KITERS = IN_F / BK;                 // 64
static constexpr int A_TILE = BM * BK * 2;               // 16 KB
static constexpr int B_TILE = BN * BK * 2;               // 16 KB
static constexpr int STAGE_BYTES = A_TILE + B_TILE;      // 32 KB
static constexpr int STAGES = 3;
static constexpr int SMEM_TOTAL = STAGES * STAGE_BYTES;  // 98304 -> 2 CTAs/SM

// Combined prep kernel split point
static constexpr int XBLOCKS = ((size_t)MROWS * IN_F) / (256 * 8);    // 4096
static constexpr int WBLOCKS = ((size_t)OUT_F * IN_F) / (256 * 16);   // 16384

// ── Scratch (device globals; no allocation) ──────────────────────────────
__device__ __half g_X16[(size_t)MROWS * IN_F];
__device__ __half g_W16[(size_t)OUT_F * IN_F];

// ── PTX helpers (sm_80-level only; family-portable) ──────────────────────
__device__ __forceinline__ uint32_t smem_u32(const void* p) {
    uint32_t a;
    asm("{ .reg .u64 t; cvta.to.shared.u64 t, %1; cvt.u32.u64 %0, t; }" : "=r"(a) : "l"(p));
    return a;
}
#define CP_ASYNC16(dst, src) \
    asm volatile("cp.async.cg.shared.global [%0], [%1], 16;" :: "r"(dst), "l"(src))
#define CP_COMMIT() asm volatile("cp.async.commit_group;" ::: "memory")
#define CP_WAIT1()  asm volatile("cp.async.wait_group 1;" ::: "memory")

__device__ __forceinline__ void ldsm4(uint32_t& r0, uint32_t& r1, uint32_t& r2, uint32_t& r3,
                                      uint32_t addr) {
    asm volatile("ldmatrix.sync.aligned.m8n8.x4.shared.b16 {%0,%1,%2,%3}, [%4];"
                 : "=r"(r0), "=r"(r1), "=r"(r2), "=r"(r3) : "r"(addr));
}
#define HMMA(c, a0, a1, a2, a3, b0, b1)                                       \
    asm volatile("mma.sync.aligned.m16n8k16.row.col.f32.f16.f16.f32 "         \
                 "{%0,%1,%2,%3},{%4,%5,%6,%7},{%8,%9},{%0,%1,%2,%3};"         \
                 : "+f"((c)[0]), "+f"((c)[1]), "+f"((c)[2]), "+f"((c)[3])     \
                 : "r"(a0), "r"(a1), "r"(a2), "r"(a3), "r"(b0), "r"(b1))

// swizzled byte offset of (row, 16B-chunk) inside a rows x 128B tile
__device__ __forceinline__ uint32_t swz(uint32_t row, uint32_t chunk) {
    return row * 128u + ((chunk ^ (row & 7u)) << 4);
}

// ── Combined prep: x fp32->fp16, W16 = ternary * fp16(scale) ─────────────
__global__ void prep_kernel(const float* __restrict__ x,
                            const int* __restrict__ tern,
                            const float* __restrict__ scales) {
    int b = blockIdx.x;
    if (b < XBLOCKS) {
        size_t i = ((size_t)b * blockDim.x + threadIdx.x) * 8;
        const float4* x4 = reinterpret_cast<const float4*>(x + i);
        float4 a = x4[0], c = x4[1];
        float v[8] = {a.x, a.y, a.z, a.w, c.x, c.y, c.z, c.w};
        union { __half h[8]; uint4 u; } o;
#pragma unroll
        for (int j = 0; j < 8; j++) o.h[j] = __float2half(v[j]);
        *reinterpret_cast<uint4*>(&g_X16[i]) = o.u;
    } else {
        size_t i = ((size_t)(b - XBLOCKS) * blockDim.x + threadIdx.x) * 16;
        const int4* t4 = reinterpret_cast<const int4*>(tern + i);
        // all 16 elems lie in one 128-wide scale group (i is a multiple of 16)
        float sf = __half2float(__float2half(scales[i >> 7]));
        union { __half h[16]; uint4 u[2]; } o;
#pragma unroll
        for (int q = 0; q < 4; q++) {
            int4 t = t4[q];
            o.h[q * 4 + 0] = __float2half(sf * (float)t.x);  // exact: t in {-1,0,1}
            o.h[q * 4 + 1] = __float2half(sf * (float)t.y);
            o.h[q * 4 + 2] = __float2half(sf * (float)t.z);
            o.h[q * 4 + 3] = __float2half(sf * (float)t.w);
        }
        uint4* dst = reinterpret_cast<uint4*>(&g_W16[i]);
        dst[0] = o.u[0];
        dst[1] = o.u[1];
    }
}

// ── GEMM: out[M,N] = X16 @ W16^T, fp32 accum in HMMA ─────────────────────
extern __shared__ __align__(128) char smem_raw[];

__global__ void __launch_bounds__(256, 2) qsgd_gemm(float* __restrict__ out)
{
    uint32_t sb = smem_u32(smem_raw);

    int tid = threadIdx.x, lane = tid & 31, wid = tid >> 5;
    int wm = wid & 1, wn = wid >> 1;          // warp grid 2(m) x 4(n): warp tile 64x32
    int gID = lane >> 2, tig = lane & 3;
    int mt0 = blockIdx.x, nt0 = blockIdx.y;   // m fastest in grid

    // ---- cp.async addressing: thread t -> row (t>>3)+32j, chunk t&7 (bytes)
    int ld_row = tid >> 3, ld_chunk = tid & 7;
    const int8_t* gA = reinterpret_cast<const int8_t*>(g_X16) +
                       (size_t)(mt0 * BM + ld_row) * (IN_F * 2) + ld_chunk * 16;
    const int8_t* gB = reinterpret_cast<const int8_t*>(g_W16) +
                       (size_t)(nt0 * BN + ld_row) * (IN_F * 2) + ld_chunk * 16;
    uint32_t st_off[4];
#pragma unroll
    for (int j = 0; j < 4; j++) st_off[j] = swz(ld_row + 32 * j, ld_chunk);

    // ---- ldmatrix per-lane address components
    uint32_t a_row_base = wm * 64 + (lane & 15);
    uint32_t a_cbit = (uint32_t)(lane >> 4);
    uint32_t b_row_base = wn * 32 + (lane & 7) + ((lane >> 4) & 1) * 8;
    uint32_t b_cbit = (uint32_t)((lane >> 3) & 1);

    float fa[4][4][4];
#pragma unroll
    for (int mt = 0; mt < 4; mt++)
#pragma unroll
        for (int nt = 0; nt < 4; nt++)
#pragma unroll
            for (int r = 0; r < 4; r++) fa[mt][nt][r] = 0.0f;

    // ---- prologue: stages 0,1
#pragma unroll
    for (int p = 0; p < 2; p++) {
        uint32_t s_a = sb + p * STAGE_BYTES;
        size_t kb = (size_t)p * (BK * 2);
#pragma unroll
        for (int j = 0; j < 4; j++) {
            size_t go = (size_t)(32 * j) * (IN_F * 2) + kb;
            CP_ASYNC16(s_a + st_off[j],          gA + go);
            CP_ASYNC16(s_a + A_TILE + st_off[j], gB + go);
        }
        CP_COMMIT();
    }

    // ---- main loop: ONE barrier per iter (wait -> sync -> issue -> compute)
    for (int it = 0; it < KITERS; it++) {
        CP_WAIT1();                 // stage `it` complete (<=1 group outstanding)
        __syncthreads();            // cross-warp visibility + frees buffer (it+2)%3

        if (it + 2 < KITERS) {
            uint32_t s_a = sb + ((it + 2) % STAGES) * STAGE_BYTES;
            size_t kb = (size_t)(it + 2) * (BK * 2);
#pragma unroll
            for (int j = 0; j < 4; j++) {
                size_t go = (size_t)(32 * j) * (IN_F * 2) + kb;
                CP_ASYNC16(s_a + st_off[j],          gA + go);
                CP_ASYNC16(s_a + A_TILE + st_off[j], gB + go);
            }
        }
        CP_COMMIT();

        uint32_t sA = sb + (it % STAGES) * STAGE_BYTES;
        uint32_t sB = sA + A_TILE;

        // 4 k16 steps cover BK=64
#pragma unroll
        for (int ks = 0; ks < 4; ks++) {
            uint32_t af[4][4];
#pragma unroll
            for (int mt = 0; mt < 4; mt++) {
                uint32_t row = a_row_base + mt * 16;
                uint32_t addr = sA + row * 128u + (((2u * ks + a_cbit) ^ (row & 7u)) << 4);
                ldsm4(af[mt][0], af[mt][1], af[mt][2], af[mt][3], addr);
            }
            uint32_t bf[4][2];
#pragma unroll
            for (int nb = 0; nb < 2; nb++) {
                uint32_t row = b_row_base + nb * 16;
                uint32_t addr = sB + row * 128u + (((2u * ks + b_cbit) ^ (row & 7u)) << 4);
                uint32_t r0, r1, r2, r3;
                ldsm4(r0, r1, r2, r3, addr);
                bf[nb * 2 + 0][0] = r0; bf[nb * 2 + 0][1] = r1;
                bf[nb * 2 + 1][0] = r2; bf[nb * 2 + 1][1] = r3;
            }
#pragma unroll
            for (int mt = 0; mt < 4; mt++)
#pragma unroll
                for (int nt = 0; nt < 4; nt++)
                    HMMA(fa[mt][nt], af[mt][0], af[mt][1], af[mt][2], af[mt][3],
                         bf[nt][0], bf[nt][1]);
        }
    }

    // ---- epilogue
#pragma unroll
    for (int mt = 0; mt < 4; mt++)
#pragma unroll
        for (int rr = 0; rr < 2; rr++) {
            int m_g = mt0 * BM + wm * 64 + mt * 16 + gID + rr * 8;
            float* op = out + (size_t)m_g * OUT_F + nt0 * BN + wn * 32 + tig * 2;
#pragma unroll
            for (int nt = 0; nt < 4; nt++) {
                float2 v;
                v.x = fa[mt][nt][rr * 2 + 0];
                v.y = fa[mt][nt][rr * 2 + 1];
                *reinterpret_cast<float2*>(op + nt * 8) = v;
            }
        }
}

// ── Host ─────────────────────────────────────────────────────────────────
extern "C" void kernel_launch(void* const* d_in, const int* in_sizes, int n_in,
                              void* d_out, int out_size) {
    const float* x      = (const float*)d_in[0];
    const int*   tern   = (const int*)d_in[1];
    const float* scales = (const float*)d_in[2];
    float* out = (float*)d_out;

    // single prep launch -> ncu -s 5 lands on qsgd_gemm (launch parity prep,gemm,...)
    prep_kernel<<<XBLOCKS + WBLOCKS, 256>>>(x, tern, scales);

    cudaFuncSetAttribute((const void*)qsgd_gemm,
                         cudaFuncAttributeMaxDynamicSharedMemorySize, SMEM_TOTAL);
    // grid: x = M tiles (fastest) so concurrent CTAs share W tiles via L2
    qsgd_gemm<<<dim3(MROWS / BM, OUT_F / BN), 256, SMEM_TOTAL>>>(out);
}